// round 5
// baseline (speedup 1.0000x reference)
#include <cuda_runtime.h>
#include <math.h>

#define Nn 100000
#define Ee 400000
#define Gg 5000
#define Hh 128
#define ND 52
#define ED 16

// ---------------- scratch (static device globals; no runtime allocation) ----------------
__device__ float g_h0[Nn * ND];        // encoded node features (52)
__device__ float g_hA[Nn * Hh];
__device__ float g_hB[Nn * Hh];
__device__ float g_xl[Nn * Hh];
__device__ float g_xr[Nn * Hh];
__device__ float g_e[(Ee + Nn) * ED];  // edge features; rows [Ee, Ee+Nn) = self-loop attrs
__device__ int   g_deg[Nn];
__device__ int   g_off[Nn + 1];
__device__ int   g_cur[Nn];
__device__ int   g_srcs[Ee];
__device__ int   g_eids[Ee];
__device__ int   g_bsums[128];

// buffer id -> device pointer (resolved on-device; keeps kernel_launch free of API calls)
#define BUF_H0 0
#define BUF_HA 1
#define BUF_HB 2
#define BUF_XL 3
#define BUF_XR 4
__device__ __forceinline__ float* bufsel(int id) {
    switch (id) {
        case BUF_H0: return g_h0;
        case BUF_HA: return g_hA;
        case BUF_HB: return g_hB;
        case BUF_XL: return g_xl;
        default:     return g_xr;
    }
}

// ---------------- zero-init (runs every launch; graph replays must be self-contained) ----
__global__ void k_zero(float* __restrict__ dout) {
    int i = blockIdx.x * blockDim.x + threadIdx.x;
    if (i < Nn * ED) g_e[(size_t)Ee * ED + i] = 0.0f;  // loop-attr accumulators
    if (i < Nn) g_deg[i] = 0;
    if (i < Gg * Hh) dout[i] = 0.0f;                   // pool output (values >= 0)
}

// ---------------- node encoder: [atom_emb(16) | x[1:11]@Wn+bn (30) | 3x bool_emb(2)] ----
__global__ void k_enc_nodes(const float* __restrict__ x,
                            const float* __restrict__ atom_emb,
                            const float* __restrict__ bool_emb,
                            const float* __restrict__ Wn,
                            const float* __restrict__ bn) {
    int n = blockIdx.x * blockDim.x + threadIdx.x;
    if (n >= Nn) return;
    const float* xr = x + (size_t)n * 14;
    float* out = g_h0 + (size_t)n * ND;
    int ai = (int)xr[0];
#pragma unroll
    for (int k = 0; k < 16; k++) out[k] = atom_emb[ai * 16 + k];
    float xc[10];
#pragma unroll
    for (int i = 0; i < 10; i++) xc[i] = xr[1 + i];
#pragma unroll
    for (int j = 0; j < 30; j++) {
        float s = bn[j];
#pragma unroll
        for (int i = 0; i < 10; i++) s += xc[i] * Wn[i * 30 + j];
        out[16 + j] = s;
    }
    int b0 = (int)xr[11], b1 = (int)xr[12], b2 = (int)xr[13];
    out[46] = bool_emb[b0 * 2];     out[47] = bool_emb[b0 * 2 + 1];
    out[48] = bool_emb[b1 * 2];     out[49] = bool_emb[b1 * 2 + 1];
    out[50] = bool_emb[b2 * 2];     out[51] = bool_emb[b2 * 2 + 1];
}

// ---------------- edge encoder + loop-attr accumulation + in-degree count --------------
__global__ void k_enc_edges(const float* __restrict__ ea,
                            const int* __restrict__ ei,
                            const float* __restrict__ bond_emb,
                            const float* __restrict__ bool_emb,
                            const float* __restrict__ We,
                            const float* __restrict__ be) {
    int e = blockIdx.x * blockDim.x + threadIdx.x;
    if (e >= Ee) return;
    const float* a = ea + (size_t)e * 6;
    float ev[ED];
    int bi = (int)a[0];
#pragma unroll
    for (int k = 0; k < 8; k++) ev[k] = bond_emb[bi * 8 + k];
    ev[8] = a[1] * We[0] + be[0];
    ev[9] = a[1] * We[1] + be[1];
    int b0 = (int)a[2], b1 = (int)a[3], b2 = (int)a[4];
    ev[10] = bool_emb[b0 * 2]; ev[11] = bool_emb[b0 * 2 + 1];
    ev[12] = bool_emb[b1 * 2]; ev[13] = bool_emb[b1 * 2 + 1];
    ev[14] = bool_emb[b2 * 2]; ev[15] = bool_emb[b2 * 2 + 1];
    float* out = g_e + (size_t)e * ED;
#pragma unroll
    for (int k = 0; k < ED; k++) out[k] = ev[k];
    int dst = ei[Ee + e];
    float* ls = g_e + ((size_t)Ee + dst) * ED;
#pragma unroll
    for (int k = 0; k < ED; k++) atomicAdd(&ls[k], ev[k]);
    atomicAdd(&g_deg[dst], 1);
}

__global__ void k_loopdiv() {
    int n = blockIdx.x * blockDim.x + threadIdx.x;
    if (n >= Nn) return;
    float inv = 1.0f / fmaxf((float)g_deg[n], 1.0f);
    float* ls = g_e + ((size_t)Ee + n) * ED;
#pragma unroll
    for (int k = 0; k < ED; k++) ls[k] *= inv;
}

// ---------------- CSR build: scan + scatter ----------------
__global__ void k_scan1() {
    __shared__ int s[1024];
    int i = blockIdx.x * 1024 + threadIdx.x;
    int v = (i < Nn) ? g_deg[i] : 0;
    s[threadIdx.x] = v;
    __syncthreads();
    for (int o = 1; o < 1024; o <<= 1) {
        int t = (threadIdx.x >= o) ? s[threadIdx.x - o] : 0;
        __syncthreads();
        s[threadIdx.x] += t;
        __syncthreads();
    }
    if (i < Nn) g_off[i] = s[threadIdx.x] - v;  // exclusive within block
    if (threadIdx.x == 1023) g_bsums[blockIdx.x] = s[1023];
}

__global__ void k_scan2(int nb) {
    if (threadIdx.x == 0) {
        int run = 0;
        for (int b = 0; b < nb; b++) { int t = g_bsums[b]; g_bsums[b] = run; run += t; }
    }
}

__global__ void k_scan3() {
    int i = blockIdx.x * blockDim.x + threadIdx.x;
    if (i < Nn) {
        int o = g_off[i] + g_bsums[i >> 10];
        g_off[i] = o;
        g_cur[i] = o;
    }
    if (i == 0) g_off[Nn] = Ee;
}

__global__ void k_scatter(const int* __restrict__ ei) {
    int e = blockIdx.x * blockDim.x + threadIdx.x;
    if (e >= Ee) return;
    int dst = ei[Ee + e];
    int p = atomicAdd(&g_cur[dst], 1);
    g_srcs[p] = ei[e];
    g_eids[p] = e;
}

// ---------------- fp32 GEMM pair: C{l,r}[Mx128] = A[MxK] @ W{l,r}[Kx128] + b{l,r} ------
// blockIdx.y = 0 -> (Wl, bl, g_xl); 1 -> (Wr, br, g_xr). A tile is shared via L2.
__global__ void k_gemm2(int a_id, int M, int K,
                        const float* __restrict__ Wl, const float* __restrict__ bl,
                        const float* __restrict__ Wr, const float* __restrict__ br) {
    const int BK = 32;
    __shared__ float As[128][BK + 1];
    __shared__ float Ws[BK][Hh];
    const float* A = bufsel(a_id);
    const float* W = blockIdx.y ? Wr : Wl;
    const float* b = blockIdx.y ? br : bl;
    float* C = blockIdx.y ? g_xr : g_xl;

    int tid = threadIdx.x;
    int tx = tid & 15, ty = tid >> 4;
    int row0 = blockIdx.x * 128;
    float acc[8][8];
#pragma unroll
    for (int i = 0; i < 8; i++)
#pragma unroll
        for (int j = 0; j < 8; j++) acc[i][j] = 0.0f;

    for (int kb = 0; kb < K; kb += BK) {
        for (int t = tid; t < 128 * BK; t += 256) {
            int r = t / BK, k = t % BK;
            int gr = row0 + r, gk = kb + k;
            As[r][k] = (gr < M && gk < K) ? A[(size_t)gr * K + gk] : 0.0f;
        }
        for (int t = tid; t < BK * Hh; t += 256) {
            int k = t >> 7, c = t & 127;
            int gk = kb + k;
            Ws[k][c] = (gk < K) ? W[(size_t)gk * Hh + c] : 0.0f;
        }
        __syncthreads();
#pragma unroll
        for (int k = 0; k < BK; k++) {
            float av[8], wv[8];
#pragma unroll
            for (int i = 0; i < 8; i++) av[i] = As[ty * 8 + i][k];
#pragma unroll
            for (int j = 0; j < 8; j++) wv[j] = Ws[k][tx * 8 + j];
#pragma unroll
            for (int i = 0; i < 8; i++)
#pragma unroll
                for (int j = 0; j < 8; j++) acc[i][j] += av[i] * wv[j];
        }
        __syncthreads();
    }
#pragma unroll
    for (int i = 0; i < 8; i++) {
        int r = row0 + ty * 8 + i;
        if (r < M) {
#pragma unroll
            for (int j = 0; j < 8; j++) {
                int c = tx * 8 + j;
                C[(size_t)r * Hh + c] = acc[i][j] + b[c];
            }
        }
    }
}

// ---------------- GATv2 aggregation: warp per node, online softmax, fused edge-linear ----
__global__ void k_gat(const float* __restrict__ Wedge, const float* __restrict__ att,
                      const float* __restrict__ bias, int hout_id,
                      int dopool, const int* __restrict__ batch, float* __restrict__ dout) {
    __shared__ float Ws[ED][Hh];
    __shared__ float atts[Hh];
    const float* xl = g_xl;
    const float* xr = g_xr;
    float* hout = bufsel(hout_id);
    int tid = threadIdx.x;
    for (int t = tid; t < ED * Hh; t += blockDim.x) Ws[t >> 7][t & 127] = Wedge[t];
    if (tid < Hh) atts[tid] = att[tid];
    __syncthreads();

    int warp = tid >> 5, lane = tid & 31;
    int n = blockIdx.x * (blockDim.x >> 5) + warp;
    if (n >= Nn) return;
    int c0 = lane * 4;

    float4 xr4 = *(const float4*)(xr + (size_t)n * Hh + c0);
    float at0 = atts[c0], at1 = atts[c0 + 1], at2 = atts[c0 + 2], at3 = atts[c0 + 3];

    float mrun = -1e30f, srun = 0.0f;
    float ac0 = 0.0f, ac1 = 0.0f, ac2 = 0.0f, ac3 = 0.0f;
    int beg = g_off[n], end = g_off[n + 1];

    for (int idx = beg; idx <= end; idx++) {
        int src, eid;
        if (idx < end) { src = g_srcs[idx]; eid = g_eids[idx]; }
        else           { src = n;           eid = Ee + n; }

        float4 xl4 = *(const float4*)(xl + (size_t)src * Hh + c0);
        const float4* evp = (const float4*)(g_e + (size_t)eid * ED);
        float4 e0 = evp[0], e1 = evp[1], e2 = evp[2], e3 = evp[3];
        float ev[ED] = {e0.x, e0.y, e0.z, e0.w, e1.x, e1.y, e1.z, e1.w,
                        e2.x, e2.y, e2.z, e2.w, e3.x, e3.y, e3.z, e3.w};
        float el0 = 0, el1 = 0, el2 = 0, el3 = 0;
#pragma unroll
        for (int j = 0; j < ED; j++) {
            float e = ev[j];
            el0 += e * Ws[j][c0];
            el1 += e * Ws[j][c0 + 1];
            el2 += e * Ws[j][c0 + 2];
            el3 += e * Ws[j][c0 + 3];
        }
        float m0 = xl4.x + xr4.x + el0;
        float m1 = xl4.y + xr4.y + el1;
        float m2 = xl4.z + xr4.z + el2;
        float m3 = xl4.w + xr4.w + el3;
        float l0 = m0 > 0.0f ? m0 : 0.2f * m0;
        float l1 = m1 > 0.0f ? m1 : 0.2f * m1;
        float l2 = m2 > 0.0f ? m2 : 0.2f * m2;
        float l3 = m3 > 0.0f ? m3 : 0.2f * m3;
        float p = l0 * at0 + l1 * at1 + l2 * at2 + l3 * at3;
#pragma unroll
        for (int o = 16; o > 0; o >>= 1) p += __shfl_xor_sync(0xffffffff, p, o);

        float nm = fmaxf(mrun, p);
        float sc = __expf(mrun - nm);
        float w  = __expf(p - nm);
        srun = srun * sc + w;
        ac0 = ac0 * sc + w * xl4.x;
        ac1 = ac1 * sc + w * xl4.y;
        ac2 = ac2 * sc + w * xl4.z;
        ac3 = ac3 * sc + w * xl4.w;
        mrun = nm;
    }

    float inv = 1.0f / srun;
    float o0 = fmaxf(ac0 * inv + bias[c0],     0.0f);
    float o1 = fmaxf(ac1 * inv + bias[c0 + 1], 0.0f);
    float o2 = fmaxf(ac2 * inv + bias[c0 + 2], 0.0f);
    float o3 = fmaxf(ac3 * inv + bias[c0 + 3], 0.0f);
    *(float4*)(hout + (size_t)n * Hh + c0) = make_float4(o0, o1, o2, o3);

    if (dopool) {
        int b = batch[n];
        int* dp = (int*)(dout + (size_t)b * Hh + c0);
        atomicMax(dp,     __float_as_int(o0));
        atomicMax(dp + 1, __float_as_int(o1));
        atomicMax(dp + 2, __float_as_int(o2));
        atomicMax(dp + 3, __float_as_int(o3));
    }
}

// ---------------- host launcher (kernel launches only; graph-capture safe) ----------------
extern "C" void kernel_launch(void* const* d_in, const int* in_sizes, int n_in,
                              void* d_out, int out_size) {
    const float* x        = (const float*)d_in[0];
    const int*   ei       = (const int*)d_in[1];
    const float* ea       = (const float*)d_in[2];
    const int*   batch    = (const int*)d_in[3];
    const float* atom_emb = (const float*)d_in[4];
    const float* bond_emb = (const float*)d_in[5];
    const float* bool_emb = (const float*)d_in[6];
    const float* Wn  = (const float*)d_in[7];
    const float* bn  = (const float*)d_in[8];
    const float* We  = (const float*)d_in[9];
    const float* be  = (const float*)d_in[10];
    const float* Wl1 = (const float*)d_in[11];
    const float* bl1 = (const float*)d_in[12];
    const float* Wr1 = (const float*)d_in[13];
    const float* br1 = (const float*)d_in[14];
    const float* Wedge1 = (const float*)d_in[15];
    const float* att1   = (const float*)d_in[16];
    const float* bias1  = (const float*)d_in[17];
    const float* Wl2 = (const float*)d_in[18];
    const float* bl2 = (const float*)d_in[19];
    const float* Wr2 = (const float*)d_in[20];
    const float* br2 = (const float*)d_in[21];
    const float* Wedge2 = (const float*)d_in[22];
    const float* att2   = (const float*)d_in[23];
    const float* bias2  = (const float*)d_in[24];
    float* out = (float*)d_out;

    // preprocessing
    k_zero<<<(Nn * ED + 255) / 256, 256>>>(out);
    k_enc_nodes<<<(Nn + 255) / 256, 256>>>(x, atom_emb, bool_emb, Wn, bn);
    k_enc_edges<<<(Ee + 255) / 256, 256>>>(ea, ei, bond_emb, bool_emb, We, be);
    k_loopdiv<<<(Nn + 255) / 256, 256>>>();
    int nb = (Nn + 1023) / 1024;
    k_scan1<<<nb, 1024>>>();
    k_scan2<<<1, 32>>>(nb);
    k_scan3<<<(Nn + 255) / 256, 256>>>();
    k_scatter<<<(Ee + 255) / 256, 256>>>(ei);

    dim3 gm((Nn + 127) / 128, 2);
    int ga = (Nn + 7) / 8;

    // layer 1 (K = 52)
    k_gemm2<<<gm, 256>>>(BUF_H0, Nn, ND, Wl1, bl1, Wr1, br1);
    k_gat<<<ga, 256>>>(Wedge1, att1, bias1, BUF_HA, 0, batch, out);

    // layer 2 (K = 128, shared weights W*2)
    k_gemm2<<<gm, 256>>>(BUF_HA, Nn, Hh, Wl2, bl2, Wr2, br2);
    k_gat<<<ga, 256>>>(Wedge2, att2, bias2, BUF_HB, 0, batch, out);

    // layer 3 (shared weights W*2) + fused global max pool
    k_gemm2<<<gm, 256>>>(BUF_HB, Nn, Hh, Wl2, bl2, Wr2, br2);
    k_gat<<<ga, 256>>>(Wedge2, att2, bias2, BUF_HA, 1, batch, out);
}

// round 6
// speedup vs baseline: 1.1083x; 1.1083x over previous
#include <cuda_runtime.h>
#include <math.h>

#define Nn 100000
#define Ee 400000
#define Gg 5000
#define Hh 128
#define ND 52
#define ED 16

// ---------------- scratch (static device globals; no runtime allocation) ----------------
__device__ float g_h0[Nn * ND];        // encoded node features (52)
__device__ float g_hA[Nn * Hh];
__device__ float g_hB[Nn * Hh];
__device__ float g_xl[Nn * Hh];
__device__ float g_xr[Nn * Hh];
__device__ float g_e[(Ee + Nn) * ED];  // edge features; rows [Ee, Ee+Nn) = self-loop attrs
__device__ int   g_deg[Nn];
__device__ int   g_off[Nn + 1];
__device__ int   g_cur[Nn];
__device__ int   g_srcs[Ee];
__device__ int   g_eids[Ee];
__device__ int   g_bsums[128];

// buffer id -> device pointer (resolved on-device; keeps kernel_launch free of API calls)
#define BUF_H0 0
#define BUF_HA 1
#define BUF_HB 2
__device__ __forceinline__ float* bufsel(int id) {
    switch (id) {
        case BUF_H0: return g_h0;
        case BUF_HA: return g_hA;
        default:     return g_hB;
    }
}

// ---------------- zero-init + node encoder (merged; independent work) ----------------
// grid covers Nn*ED threads (largest need). Threads also zero pool output and deg,
// and threads < Nn encode node features.
__global__ void k_init_nodes(const float* __restrict__ x,
                             const float* __restrict__ atom_emb,
                             const float* __restrict__ bool_emb,
                             const float* __restrict__ Wn,
                             const float* __restrict__ bn,
                             float* __restrict__ dout) {
    int i = blockIdx.x * blockDim.x + threadIdx.x;
    if (i < Nn * ED) g_e[(size_t)Ee * ED + i] = 0.0f;   // loop-attr accumulators
    if (i < Gg * Hh) dout[i] = 0.0f;                     // pool output (values >= 0)
    if (i < Nn) g_deg[i] = 0;

    int n = i;
    if (n >= Nn) return;
    const float* xr = x + (size_t)n * 14;
    float* out = g_h0 + (size_t)n * ND;
    int ai = (int)xr[0];
#pragma unroll
    for (int k = 0; k < 16; k++) out[k] = atom_emb[ai * 16 + k];
    float xc[10];
#pragma unroll
    for (int i2 = 0; i2 < 10; i2++) xc[i2] = xr[1 + i2];
#pragma unroll
    for (int j = 0; j < 30; j++) {
        float s = bn[j];
#pragma unroll
        for (int i2 = 0; i2 < 10; i2++) s += xc[i2] * Wn[i2 * 30 + j];
        out[16 + j] = s;
    }
    int b0 = (int)xr[11], b1 = (int)xr[12], b2 = (int)xr[13];
    out[46] = bool_emb[b0 * 2];     out[47] = bool_emb[b0 * 2 + 1];
    out[48] = bool_emb[b1 * 2];     out[49] = bool_emb[b1 * 2 + 1];
    out[50] = bool_emb[b2 * 2];     out[51] = bool_emb[b2 * 2 + 1];
}

// ---------------- edge encoder + loop-attr accumulation + in-degree count --------------
__global__ void k_enc_edges(const float* __restrict__ ea,
                            const int* __restrict__ ei,
                            const float* __restrict__ bond_emb,
                            const float* __restrict__ bool_emb,
                            const float* __restrict__ We,
                            const float* __restrict__ be) {
    int e = blockIdx.x * blockDim.x + threadIdx.x;
    if (e >= Ee) return;
    const float* a = ea + (size_t)e * 6;
    float ev[ED];
    int bi = (int)a[0];
#pragma unroll
    for (int k = 0; k < 8; k++) ev[k] = bond_emb[bi * 8 + k];
    ev[8] = a[1] * We[0] + be[0];
    ev[9] = a[1] * We[1] + be[1];
    int b0 = (int)a[2], b1 = (int)a[3], b2 = (int)a[4];
    ev[10] = bool_emb[b0 * 2]; ev[11] = bool_emb[b0 * 2 + 1];
    ev[12] = bool_emb[b1 * 2]; ev[13] = bool_emb[b1 * 2 + 1];
    ev[14] = bool_emb[b2 * 2]; ev[15] = bool_emb[b2 * 2 + 1];
    float* out = g_e + (size_t)e * ED;
#pragma unroll
    for (int k = 0; k < ED; k++) out[k] = ev[k];
    int dst = ei[Ee + e];
    float* ls = g_e + ((size_t)Ee + dst) * ED;
#pragma unroll
    for (int k = 0; k < ED; k++) atomicAdd(&ls[k], ev[k]);
    atomicAdd(&g_deg[dst], 1);
}

// ---------------- CSR scan (block-level) + loop-attr mean division (merged) ------------
__global__ void k_scan1() {
    __shared__ int s[1024];
    int i = blockIdx.x * 1024 + threadIdx.x;
    int v = (i < Nn) ? g_deg[i] : 0;
    // loop-attr division (needs final deg + e sums; both ready before this kernel)
    if (i < Nn) {
        float inv = 1.0f / fmaxf((float)v, 1.0f);
        float* ls = g_e + ((size_t)Ee + i) * ED;
#pragma unroll
        for (int k = 0; k < ED; k++) ls[k] *= inv;
    }
    s[threadIdx.x] = v;
    __syncthreads();
    for (int o = 1; o < 1024; o <<= 1) {
        int t = (threadIdx.x >= o) ? s[threadIdx.x - o] : 0;
        __syncthreads();
        s[threadIdx.x] += t;
        __syncthreads();
    }
    if (i < Nn) g_off[i] = s[threadIdx.x] - v;  // exclusive within block
    if (threadIdx.x == 1023) g_bsums[blockIdx.x] = s[1023];
}

__global__ void k_scan2(int nb) {
    if (threadIdx.x == 0) {
        int run = 0;
        for (int b = 0; b < nb; b++) { int t = g_bsums[b]; g_bsums[b] = run; run += t; }
    }
}

__global__ void k_scan3() {
    int i = blockIdx.x * blockDim.x + threadIdx.x;
    if (i < Nn) {
        int o = g_off[i] + g_bsums[i >> 10];
        g_off[i] = o;
        g_cur[i] = o;
    }
    if (i == 0) g_off[Nn] = Ee;
}

__global__ void k_scatter(const int* __restrict__ ei) {
    int e = blockIdx.x * blockDim.x + threadIdx.x;
    if (e >= Ee) return;
    int dst = ei[Ee + e];
    int p = atomicAdd(&g_cur[dst], 1);
    g_srcs[p] = ei[e];
    g_eids[p] = e;
}

// ---------------- fused fp32 GEMM pair: [xl | xr] = A[MxK] @ [Wl | Wr] + [bl | br] -----
// One block: 128 rows x 256 cols (128 -> xl, 128 -> xr). 512 threads, 8x8 micro-tile.
// Thread map: tx = tid&31 (col lane), ty = tid>>5 (row group). Thread cols: j*32+tx
// (stride-32 -> conflict-free LDS); thread rows: ty*8+i (broadcast LDS).
__global__ __launch_bounds__(512) void k_gemm2(int a_id, int M, int K,
                        const float* __restrict__ Wl, const float* __restrict__ bl,
                        const float* __restrict__ Wr, const float* __restrict__ br) {
    const int BK = 16;
    __shared__ float As[128][20];    // 20-float row stride: 16B-aligned, de-conflicted
    __shared__ float Ws[BK][256];
    const float* A = bufsel(a_id);

    int tid = threadIdx.x;
    int tx = tid & 31, ty = tid >> 5;
    int row0 = blockIdx.x * 128;

    float acc[8][8];
#pragma unroll
    for (int i = 0; i < 8; i++)
#pragma unroll
        for (int j = 0; j < 8; j++) acc[i][j] = 0.0f;

    // A-tile load indices (1 float4 per thread per iter)
    int ar = tid >> 2;              // 0..127
    int ac4 = (tid & 3) << 2;       // 0,4,8,12
    int gr = row0 + ar;

    for (int kb = 0; kb < K; kb += BK) {
        // load A tile [128 x 16]
        {
            float4 v = make_float4(0.f, 0.f, 0.f, 0.f);
            int gk = kb + ac4;
            if (gr < M) {
                const float* ap = A + (size_t)gr * K + gk;
                if (gk + 3 < K) {
                    v = *(const float4*)ap;
                } else {
                    if (gk     < K) v.x = ap[0];
                    if (gk + 1 < K) v.y = ap[1];
                    if (gk + 2 < K) v.z = ap[2];
                    if (gk + 3 < K) v.w = ap[3];
                }
            }
            *(float4*)&As[ar][ac4] = v;
        }
        // load W tile [16 x 256] = [Wl chunk | Wr chunk]
#pragma unroll
        for (int t = tid; t < BK * 64; t += 512) {
            int k = t >> 6;
            int c4 = (t & 63) << 2;
            int gk = kb + k;
            float4 v = make_float4(0.f, 0.f, 0.f, 0.f);
            if (gk < K) {
                v = (c4 < 128) ? *(const float4*)(Wl + (size_t)gk * 128 + c4)
                               : *(const float4*)(Wr + (size_t)gk * 128 + (c4 - 128));
            }
            *(float4*)&Ws[k][c4] = v;
        }
        __syncthreads();

#pragma unroll
        for (int k = 0; k < BK; k++) {
            float av[8], wv[8];
#pragma unroll
            for (int i = 0; i < 8; i++) av[i] = As[ty * 8 + i][k];
#pragma unroll
            for (int j = 0; j < 8; j++) wv[j] = Ws[k][j * 32 + tx];
#pragma unroll
            for (int i = 0; i < 8; i++)
#pragma unroll
                for (int j = 0; j < 8; j++) acc[i][j] += av[i] * wv[j];
        }
        __syncthreads();
    }

#pragma unroll
    for (int i = 0; i < 8; i++) {
        int r = row0 + ty * 8 + i;
        if (r < M) {
#pragma unroll
            for (int j = 0; j < 4; j++) {
                int c = j * 32 + tx;
                g_xl[(size_t)r * Hh + c] = acc[i][j] + bl[c];
            }
#pragma unroll
            for (int j = 4; j < 8; j++) {
                int c = (j - 4) * 32 + tx;
                g_xr[(size_t)r * Hh + c] = acc[i][j + 0] + br[c];
            }
        }
    }
}

// ---------------- GATv2 aggregation: warp per node, online softmax, fused edge-linear ----
__global__ void k_gat(const float* __restrict__ Wedge, const float* __restrict__ att,
                      const float* __restrict__ bias, int hout_id,
                      int dopool, const int* __restrict__ batch, float* __restrict__ dout) {
    __shared__ float Ws[ED][Hh];
    __shared__ float atts[Hh];
    const float* xl = g_xl;
    const float* xr = g_xr;
    float* hout = bufsel(hout_id);
    int tid = threadIdx.x;
    for (int t = tid; t < ED * Hh; t += blockDim.x) Ws[t >> 7][t & 127] = Wedge[t];
    if (tid < Hh) atts[tid] = att[tid];
    __syncthreads();

    int warp = tid >> 5, lane = tid & 31;
    int n = blockIdx.x * (blockDim.x >> 5) + warp;
    if (n >= Nn) return;
    int c0 = lane * 4;

    float4 xr4 = *(const float4*)(xr + (size_t)n * Hh + c0);
    float at0 = atts[c0], at1 = atts[c0 + 1], at2 = atts[c0 + 2], at3 = atts[c0 + 3];

    float mrun = -1e30f, srun = 0.0f;
    float ac0 = 0.0f, ac1 = 0.0f, ac2 = 0.0f, ac3 = 0.0f;
    int beg = g_off[n], end = g_off[n + 1];

    for (int idx = beg; idx <= end; idx++) {
        int src, eid;
        if (idx < end) { src = g_srcs[idx]; eid = g_eids[idx]; }
        else           { src = n;           eid = Ee + n; }

        float4 xl4 = *(const float4*)(xl + (size_t)src * Hh + c0);
        const float4* evp = (const float4*)(g_e + (size_t)eid * ED);
        float4 e0 = evp[0], e1 = evp[1], e2 = evp[2], e3 = evp[3];
        float ev[ED] = {e0.x, e0.y, e0.z, e0.w, e1.x, e1.y, e1.z, e1.w,
                        e2.x, e2.y, e2.z, e2.w, e3.x, e3.y, e3.z, e3.w};
        float el0 = 0, el1 = 0, el2 = 0, el3 = 0;
#pragma unroll
        for (int j = 0; j < ED; j++) {
            float e = ev[j];
            el0 += e * Ws[j][c0];
            el1 += e * Ws[j][c0 + 1];
            el2 += e * Ws[j][c0 + 2];
            el3 += e * Ws[j][c0 + 3];
        }
        float m0 = xl4.x + xr4.x + el0;
        float m1 = xl4.y + xr4.y + el1;
        float m2 = xl4.z + xr4.z + el2;
        float m3 = xl4.w + xr4.w + el3;
        float l0 = m0 > 0.0f ? m0 : 0.2f * m0;
        float l1 = m1 > 0.0f ? m1 : 0.2f * m1;
        float l2 = m2 > 0.0f ? m2 : 0.2f * m2;
        float l3 = m3 > 0.0f ? m3 : 0.2f * m3;
        float p = l0 * at0 + l1 * at1 + l2 * at2 + l3 * at3;
#pragma unroll
        for (int o = 16; o > 0; o >>= 1) p += __shfl_xor_sync(0xffffffff, p, o);

        float nm = fmaxf(mrun, p);
        float sc = expf(mrun - nm);
        float w  = expf(p - nm);
        srun = srun * sc + w;
        ac0 = ac0 * sc + w * xl4.x;
        ac1 = ac1 * sc + w * xl4.y;
        ac2 = ac2 * sc + w * xl4.z;
        ac3 = ac3 * sc + w * xl4.w;
        mrun = nm;
    }

    float inv = 1.0f / srun;
    float o0 = fmaxf(ac0 * inv + bias[c0],     0.0f);
    float o1 = fmaxf(ac1 * inv + bias[c0 + 1], 0.0f);
    float o2 = fmaxf(ac2 * inv + bias[c0 + 2], 0.0f);
    float o3 = fmaxf(ac3 * inv + bias[c0 + 3], 0.0f);
    *(float4*)(hout + (size_t)n * Hh + c0) = make_float4(o0, o1, o2, o3);

    if (dopool) {
        int b = batch[n];
        int* dp = (int*)(dout + (size_t)b * Hh + c0);
        atomicMax(dp,     __float_as_int(o0));
        atomicMax(dp + 1, __float_as_int(o1));
        atomicMax(dp + 2, __float_as_int(o2));
        atomicMax(dp + 3, __float_as_int(o3));
    }
}

// ---------------- host launcher (kernel launches only; graph-capture safe) ----------------
extern "C" void kernel_launch(void* const* d_in, const int* in_sizes, int n_in,
                              void* d_out, int out_size) {
    const float* x        = (const float*)d_in[0];
    const int*   ei       = (const int*)d_in[1];
    const float* ea       = (const float*)d_in[2];
    const int*   batch    = (const int*)d_in[3];
    const float* atom_emb = (const float*)d_in[4];
    const float* bond_emb = (const float*)d_in[5];
    const float* bool_emb = (const float*)d_in[6];
    const float* Wn  = (const float*)d_in[7];
    const float* bn  = (const float*)d_in[8];
    const float* We  = (const float*)d_in[9];
    const float* be  = (const float*)d_in[10];
    const float* Wl1 = (const float*)d_in[11];
    const float* bl1 = (const float*)d_in[12];
    const float* Wr1 = (const float*)d_in[13];
    const float* br1 = (const float*)d_in[14];
    const float* Wedge1 = (const float*)d_in[15];
    const float* att1   = (const float*)d_in[16];
    const float* bias1  = (const float*)d_in[17];
    const float* Wl2 = (const float*)d_in[18];
    const float* bl2 = (const float*)d_in[19];
    const float* Wr2 = (const float*)d_in[20];
    const float* br2 = (const float*)d_in[21];
    const float* Wedge2 = (const float*)d_in[22];
    const float* att2   = (const float*)d_in[23];
    const float* bias2  = (const float*)d_in[24];
    float* out = (float*)d_out;

    // preprocessing
    k_init_nodes<<<(Nn * ED + 255) / 256, 256>>>(x, atom_emb, bool_emb, Wn, bn, out);
    k_enc_edges<<<(Ee + 255) / 256, 256>>>(ea, ei, bond_emb, bool_emb, We, be);
    int nb = (Nn + 1023) / 1024;
    k_scan1<<<nb, 1024>>>();
    k_scan2<<<1, 32>>>(nb);
    k_scan3<<<(Nn + 255) / 256, 256>>>();
    k_scatter<<<(Ee + 255) / 256, 256>>>(ei);

    int gm = (Nn + 127) / 128;
    int ga = (Nn + 7) / 8;

    // layer 1 (K = 52)
    k_gemm2<<<gm, 512>>>(BUF_H0, Nn, ND, Wl1, bl1, Wr1, br1);
    k_gat<<<ga, 256>>>(Wedge1, att1, bias1, BUF_HA, 0, batch, out);

    // layer 2 (K = 128, shared weights W*2)
    k_gemm2<<<gm, 512>>>(BUF_HA, Nn, Hh, Wl2, bl2, Wr2, br2);
    k_gat<<<ga, 256>>>(Wedge2, att2, bias2, BUF_HB, 0, batch, out);

    // layer 3 (shared weights W*2) + fused global max pool
    k_gemm2<<<gm, 512>>>(BUF_HB, Nn, Hh, Wl2, bl2, Wr2, br2);
    k_gat<<<ga, 256>>>(Wedge2, att2, bias2, BUF_HA, 1, batch, out);
}